// round 14
// baseline (speedup 1.0000x reference)
#include <cuda_runtime.h>
#include <stdint.h>
#include <math.h>

#define Bn    8
#define LIN   4096
#define Dn    256
#define MAXT  2048
#define OUT_ELEMS (Bn * MAXT * Dn)        // 4,194,304
#define NOISE_SCALE 0.1f
#define EPSV 1e-12f

__device__ int g_L[Bn];

// ---------------------------------------------------------------------------
// Count valid tokens per batch. Mask dtype sniffed at runtime:
//   int32  : words in {0,1}
//   float32: words contain 0x3F800000
//   uint8  : byte-packed 0/1 -> pad runs give 0x01010101 words
// ---------------------------------------------------------------------------
__global__ void count_valid_kernel(const void* __restrict__ maskv) {
    int b = blockIdx.x;
    const unsigned int* words = (const unsigned int*)maskv;
    int f32f = 0, u8f = 0;
    for (int i = threadIdx.x; i < 8192; i += blockDim.x) {
        unsigned int w = words[i];
        f32f |= (w == 0x3F800000u);
        u8f  |= (w == 0x01010101u);
    }
    int isf32 = __syncthreads_or(f32f);
    int isu8  = __syncthreads_or(u8f);

    int cnt = 0;
    if (isf32) {
        const float* m = (const float*)maskv;
        for (int i = threadIdx.x; i < LIN; i += blockDim.x)
            cnt += (m[b * LIN + i] == 0.0f) ? 1 : 0;
    } else if (isu8) {
        const unsigned char* m = (const unsigned char*)maskv;
        for (int i = threadIdx.x; i < LIN; i += blockDim.x)
            cnt += (m[b * LIN + i] == 0) ? 1 : 0;
    } else {
        const int* m = (const int*)maskv;
        for (int i = threadIdx.x; i < LIN; i += blockDim.x)
            cnt += (m[b * LIN + i] == 0) ? 1 : 0;
    }
    __shared__ int sh[8];
    for (int o = 16; o; o >>= 1) cnt += __shfl_down_sync(0xFFFFFFFFu, cnt, o);
    if ((threadIdx.x & 31) == 0) sh[threadIdx.x >> 5] = cnt;
    __syncthreads();
    if (threadIdx.x == 0) {
        int s = 0;
        #pragma unroll
        for (int i = 0; i < 8; i++) s += sh[i];
        g_L[b] = s;
    }
}

// ---------------------------------------------------------------------------
// Threefry-2x32, 20 rounds, key = (0, 42)  (jax.random.key(42))
// ---------------------------------------------------------------------------
__device__ __forceinline__ void threefry2x32(unsigned int& v0, unsigned int& v1) {
    const unsigned int ks0 = 0u;
    const unsigned int ks1 = 42u;
    const unsigned int ks2 = 0x1BD11BDAu ^ 42u;
    v0 += ks0; v1 += ks1;
#define TF_RND(r) { v0 += v1; v1 = __funnelshift_l(v1, v1, (r)); v1 ^= v0; }
    TF_RND(13) TF_RND(15) TF_RND(26) TF_RND(6)
    v0 += ks1; v1 += ks2 + 1u;
    TF_RND(17) TF_RND(29) TF_RND(16) TF_RND(24)
    v0 += ks2; v1 += ks0 + 2u;
    TF_RND(13) TF_RND(15) TF_RND(26) TF_RND(6)
    v0 += ks0; v1 += ks1 + 3u;
    TF_RND(17) TF_RND(29) TF_RND(16) TF_RND(24)
    v0 += ks1; v1 += ks2 + 4u;
    TF_RND(13) TF_RND(15) TF_RND(26) TF_RND(6)
    v0 += ks2; v1 += ks0 + 5u;
#undef TF_RND
}

// XLA/Giles single-precision erfinv (matches xla math.cc ErfInv 32-bit path)
__device__ __forceinline__ float erfinv_xla(float x) {
    float w = -log1pf(-x * x);
    float p;
    if (w < 5.0f) {
        w -= 2.5f;
        p =              2.81022636e-08f;
        p = fmaf(p, w,   3.43273939e-07f);
        p = fmaf(p, w,  -3.5233877e-06f);
        p = fmaf(p, w,  -4.39150654e-06f);
        p = fmaf(p, w,   0.00021858087f);
        p = fmaf(p, w,  -0.00125372503f);
        p = fmaf(p, w,  -0.00417768164f);
        p = fmaf(p, w,   0.246640727f);
        p = fmaf(p, w,   1.50140941f);
    } else {
        w = sqrtf(w) - 3.0f;
        p =             -0.000200214257f;
        p = fmaf(p, w,   0.000100950558f);
        p = fmaf(p, w,   0.00134934322f);
        p = fmaf(p, w,  -0.00367342844f);
        p = fmaf(p, w,   0.00573950773f);
        p = fmaf(p, w,  -0.0076224613f);
        p = fmaf(p, w,   0.00943887047f);
        p = fmaf(p, w,   1.00167406f);
        p = fmaf(p, w,   2.83297682f);
    }
    return p * x;
}

// bits -> jax.random.normal sample:
//   f = bitcast((bits>>9) | 0x3f800000) - 1      in [0,1)
//   u = max(lo, f*2.0f + lo), lo = nextafter(-1,0)
//   eps = sqrt(2) * erfinv(u)
__device__ __forceinline__ float bits_to_normal(unsigned int bits) {
    const float lo = -0.99999994f;
    float f = __uint_as_float((bits >> 9) | 0x3F800000u) - 1.0f;
    float u = fmaxf(lo, fmaf(f, 2.0f, lo));
    return 1.41421354f * erfinv_xla(u);
}

// Partitionable-threefry 32-bit random bits for flat index idx (< 2^32):
//   counter = (hi, lo) = (0, idx);  bits = v0_out ^ v1_out
__device__ __forceinline__ unsigned int jax_random_bits_part(unsigned int idx) {
    unsigned int v0 = 0u, v1 = idx;
    threefry2x32(v0, v1);
    return v0 ^ v1;
}

// ---------------------------------------------------------------------------
// Bin parameters (shared per block; all d lanes of a (b,t) share them)
// ---------------------------------------------------------------------------
struct BinParams {
    int   i0, i1, lo, hi, valid;
    float start, end, invcnt;
};

__device__ __forceinline__ void make_params(int t, int L, int T, BinParams& p) {
    p.valid = (t < T) && (L > 0);
    if (!p.valid) { p.i0 = p.i1 = p.lo = 0; p.hi = -1; p.start = p.end = 0.f; p.invcnt = 1.f; return; }
    int Tc = (T > 1) ? T : 1;
    int jL = t * L;
    p.i0 = jL / Tc;
    p.i1 = (jL + L + Tc - 1) / Tc;
    float step = (float)L / (float)Tc;
    p.start = (float)t * step;
    p.end   = p.start + step;
    int flo = (int)floorf(p.start); if (flo < 0) flo = 0;
    int fhi = (int)floorf(p.end);   if (fhi > L - 1) fhi = L - 1;
    p.lo = min(p.i0, flo);
    p.hi = max(p.i1 - 1, fhi);
    p.invcnt = 1.0f / (float)(p.i1 - p.i0);
}

__device__ __forceinline__ float bin_value(const float* __restrict__ xcol,
                                           const BinParams& p, float eps) {
    if (!p.valid) return 0.0f;
    float sInt = 0.f, sW = 0.f, sWS = 0.f, sWS2 = 0.f;
    #pragma unroll 4
    for (int i = p.lo; i <= p.hi; ++i) {
        float s = __ldg(xcol + (size_t)i * Dn);
        if (i >= p.i0 && i < p.i1) sInt += s;
        float fi = (float)i;
        float w = fmaxf(fminf(fi + 1.0f, p.end) - fmaxf(fi, p.start), 0.0f);
        sW  += w;
        sWS  = fmaf(w, s, sWS);
        sWS2 = fmaf(w * s, s, sWS2);
    }
    float Wsum = fmaxf(sW, EPSV);
    float mean = sWS  / Wsum;
    float msq  = sWS2 / Wsum;
    float var  = fmaxf(msq - mean * mean, EPSV);
    float std  = sqrtf(var);
    return fmaf(eps * std, NOISE_SCALE, sInt * p.invcnt);
}

// ---------------------------------------------------------------------------
// Main kernel: one block per (b, t) bin; thread = d lane.
// ---------------------------------------------------------------------------
__global__ void __launch_bounds__(256)
resamp_kernel(const float* __restrict__ x, const int* __restrict__ fl,
              float* __restrict__ out) {
    __shared__ BinParams p;
    int bt = blockIdx.x;                 // b*MAXT + t
    int b  = bt >> 11;                   // / MAXT
    int t  = bt & (MAXT - 1);
    if (threadIdx.x == 0) make_params(t, g_L[b], fl[b], p);
    __syncthreads();

    int d = threadIdx.x;
    unsigned int idx = (unsigned int)bt * Dn + d;   // flat (b,t,d) index
    float eps = bits_to_normal(jax_random_bits_part(idx));

    const float* xcol = x + ((size_t)b * LIN) * Dn + d;
    out[idx] = bin_value(xcol, p, eps);
}

// Optional out_mask tail (True = pad), written as float or byte per out_size.
__global__ void mask_kernel_f32(const int* __restrict__ fl, float* __restrict__ mo) {
    int i = blockIdx.x * blockDim.x + threadIdx.x;
    if (i >= Bn * MAXT) return;
    int b = i >> 11, t = i & (MAXT - 1);
    bool valid = (t < fl[b]) && (g_L[b] > 0);
    mo[i] = valid ? 0.0f : 1.0f;
}
__global__ void mask_kernel_u8(const int* __restrict__ fl, unsigned char* __restrict__ mo) {
    int i = blockIdx.x * blockDim.x + threadIdx.x;
    if (i >= Bn * MAXT) return;
    int b = i >> 11, t = i & (MAXT - 1);
    bool valid = (t < fl[b]) && (g_L[b] > 0);
    mo[i] = valid ? 0 : 1;
}

extern "C" void kernel_launch(void* const* d_in, const int* in_sizes, int n_in,
                              void* d_out, int out_size) {
    const float* x    = (const float*)d_in[0];
    const int*   fl   = (const int*)d_in[1];
    const void*  mask = (const void*)d_in[2];
    float* out = (float*)d_out;

    count_valid_kernel<<<Bn, 256>>>(mask);
    resamp_kernel<<<Bn * MAXT, 256>>>(x, fl, out);

    long long extra = (long long)out_size - (long long)OUT_ELEMS;
    if (extra >= (long long)(Bn * MAXT)) {
        // mask appended as float32 elements
        mask_kernel_f32<<<(Bn * MAXT + 255) / 256, 256>>>(fl, out + OUT_ELEMS);
    } else if (extra == (long long)(Bn * MAXT) / 4) {
        // mask appended as packed bytes occupying (B*MAXT)/4 float slots
        mask_kernel_u8<<<(Bn * MAXT + 255) / 256, 256>>>(
            fl, (unsigned char*)(out + OUT_ELEMS));
    }
}

// round 15
// speedup vs baseline: 1.0444x; 1.0444x over previous
#include <cuda_runtime.h>
#include <stdint.h>
#include <math.h>

#define Bn    8
#define LIN   4096
#define Dn    256
#define MAXT  2048
#define OUT_ELEMS (Bn * MAXT * Dn)        // 4,194,304
#define NOISE_SCALE 0.1f
#define EPSV 1e-12f

__device__ int g_L[Bn];

// ---------------------------------------------------------------------------
// Count valid tokens per batch. Mask dtype sniffed at runtime:
//   int32  : words in {0,1}
//   float32: words contain 0x3F800000
//   uint8  : byte-packed 0/1 -> pad runs give 0x01010101 words
// 1024 threads/block: 8 sniff loads + 4 count loads per thread (high MLP,
// short dependent chains) instead of 32+16 with 256 threads.
// ---------------------------------------------------------------------------
__global__ void __launch_bounds__(1024)
count_valid_kernel(const void* __restrict__ maskv) {
    int b = blockIdx.x;
    const unsigned int* words = (const unsigned int*)maskv;
    int f32f = 0, u8f = 0;
    #pragma unroll
    for (int k = 0; k < 8; k++) {
        unsigned int w = words[k * 1024 + threadIdx.x];
        f32f |= (w == 0x3F800000u);
        u8f  |= (w == 0x01010101u);
    }
    int isf32 = __syncthreads_or(f32f);
    int isu8  = __syncthreads_or(u8f);

    int cnt = 0;
    if (isf32) {
        const float* m = (const float*)maskv + b * LIN;
        #pragma unroll
        for (int k = 0; k < 4; k++)
            cnt += (m[k * 1024 + threadIdx.x] == 0.0f) ? 1 : 0;
    } else if (isu8) {
        const unsigned char* m = (const unsigned char*)maskv + b * LIN;
        #pragma unroll
        for (int k = 0; k < 4; k++)
            cnt += (m[k * 1024 + threadIdx.x] == 0) ? 1 : 0;
    } else {
        const int* m = (const int*)maskv + b * LIN;
        #pragma unroll
        for (int k = 0; k < 4; k++)
            cnt += (m[k * 1024 + threadIdx.x] == 0) ? 1 : 0;
    }
    __shared__ int sh[32];
    for (int o = 16; o; o >>= 1) cnt += __shfl_down_sync(0xFFFFFFFFu, cnt, o);
    if ((threadIdx.x & 31) == 0) sh[threadIdx.x >> 5] = cnt;
    __syncthreads();
    if (threadIdx.x < 32) {
        int s = sh[threadIdx.x];
        for (int o = 16; o; o >>= 1) s += __shfl_down_sync(0xFFFFFFFFu, s, o);
        if (threadIdx.x == 0) g_L[b] = s;
    }
}

// ---------------------------------------------------------------------------
// Threefry-2x32, 20 rounds, key = (0, 42)  (jax.random.key(42))
// ---------------------------------------------------------------------------
__device__ __forceinline__ void threefry2x32(unsigned int& v0, unsigned int& v1) {
    const unsigned int ks0 = 0u;
    const unsigned int ks1 = 42u;
    const unsigned int ks2 = 0x1BD11BDAu ^ 42u;
    v0 += ks0; v1 += ks1;
#define TF_RND(r) { v0 += v1; v1 = __funnelshift_l(v1, v1, (r)); v1 ^= v0; }
    TF_RND(13) TF_RND(15) TF_RND(26) TF_RND(6)
    v0 += ks1; v1 += ks2 + 1u;
    TF_RND(17) TF_RND(29) TF_RND(16) TF_RND(24)
    v0 += ks2; v1 += ks0 + 2u;
    TF_RND(13) TF_RND(15) TF_RND(26) TF_RND(6)
    v0 += ks0; v1 += ks1 + 3u;
    TF_RND(17) TF_RND(29) TF_RND(16) TF_RND(24)
    v0 += ks1; v1 += ks2 + 4u;
    TF_RND(13) TF_RND(15) TF_RND(26) TF_RND(6)
    v0 += ks2; v1 += ks0 + 5u;
#undef TF_RND
}

// XLA/Giles single-precision erfinv (matches xla math.cc ErfInv 32-bit path)
__device__ __forceinline__ float erfinv_xla(float x) {
    float w = -log1pf(-x * x);
    float p;
    if (w < 5.0f) {
        w -= 2.5f;
        p =              2.81022636e-08f;
        p = fmaf(p, w,   3.43273939e-07f);
        p = fmaf(p, w,  -3.5233877e-06f);
        p = fmaf(p, w,  -4.39150654e-06f);
        p = fmaf(p, w,   0.00021858087f);
        p = fmaf(p, w,  -0.00125372503f);
        p = fmaf(p, w,  -0.00417768164f);
        p = fmaf(p, w,   0.246640727f);
        p = fmaf(p, w,   1.50140941f);
    } else {
        w = sqrtf(w) - 3.0f;
        p =             -0.000200214257f;
        p = fmaf(p, w,   0.000100950558f);
        p = fmaf(p, w,   0.00134934322f);
        p = fmaf(p, w,  -0.00367342844f);
        p = fmaf(p, w,   0.00573950773f);
        p = fmaf(p, w,  -0.0076224613f);
        p = fmaf(p, w,   0.00943887047f);
        p = fmaf(p, w,   1.00167406f);
        p = fmaf(p, w,   2.83297682f);
    }
    return p * x;
}

// bits -> jax.random.normal sample:
//   f = bitcast((bits>>9) | 0x3f800000) - 1      in [0,1)
//   u = max(lo, f*2.0f + lo), lo = nextafter(-1,0)
//   eps = sqrt(2) * erfinv(u)
__device__ __forceinline__ float bits_to_normal(unsigned int bits) {
    const float lo = -0.99999994f;
    float f = __uint_as_float((bits >> 9) | 0x3F800000u) - 1.0f;
    float u = fmaxf(lo, fmaf(f, 2.0f, lo));
    return 1.41421354f * erfinv_xla(u);
}

// Partitionable-threefry 32-bit random bits for flat index idx (< 2^32):
//   counter = (hi, lo) = (0, idx);  bits = v0_out ^ v1_out
__device__ __forceinline__ unsigned int jax_random_bits_part(unsigned int idx) {
    unsigned int v0 = 0u, v1 = idx;
    threefry2x32(v0, v1);
    return v0 ^ v1;
}

// ---------------------------------------------------------------------------
// Bin parameters (shared per block; all d lanes of a (b,t) share them)
// ---------------------------------------------------------------------------
struct BinParams {
    int   i0, i1, lo, hi, valid;
    float start, end, invcnt;
};

__device__ __forceinline__ void make_params(int t, int L, int T, BinParams& p) {
    p.valid = (t < T) && (L > 0);
    if (!p.valid) { p.i0 = p.i1 = p.lo = 0; p.hi = -1; p.start = p.end = 0.f; p.invcnt = 1.f; return; }
    int Tc = (T > 1) ? T : 1;
    int jL = t * L;
    p.i0 = jL / Tc;
    p.i1 = (jL + L + Tc - 1) / Tc;
    float step = (float)L / (float)Tc;
    p.start = (float)t * step;
    p.end   = p.start + step;
    int flo = (int)floorf(p.start); if (flo < 0) flo = 0;
    int fhi = (int)floorf(p.end);   if (fhi > L - 1) fhi = L - 1;
    p.lo = min(p.i0, flo);
    p.hi = max(p.i1 - 1, fhi);
    p.invcnt = 1.0f / (float)(p.i1 - p.i0);
}

__device__ __forceinline__ float bin_value(const float* __restrict__ xcol,
                                           const BinParams& p, float eps) {
    if (!p.valid) return 0.0f;
    float sInt = 0.f, sW = 0.f, sWS = 0.f, sWS2 = 0.f;
    #pragma unroll 4
    for (int i = p.lo; i <= p.hi; ++i) {
        float s = __ldg(xcol + (size_t)i * Dn);
        if (i >= p.i0 && i < p.i1) sInt += s;
        float fi = (float)i;
        float w = fmaxf(fminf(fi + 1.0f, p.end) - fmaxf(fi, p.start), 0.0f);
        sW  += w;
        sWS  = fmaf(w, s, sWS);
        sWS2 = fmaf(w * s, s, sWS2);
    }
    float Wsum = fmaxf(sW, EPSV);
    float mean = sWS  / Wsum;
    float msq  = sWS2 / Wsum;
    float var  = fmaxf(msq - mean * mean, EPSV);
    float std  = sqrtf(var);
    return fmaf(eps * std, NOISE_SCALE, sInt * p.invcnt);
}

// ---------------------------------------------------------------------------
// Main kernel: one block per (b, t) bin; thread = d lane.
// Thread 0 also writes the output mask element (if requested), removing the
// separate mask kernel launch.
// ---------------------------------------------------------------------------
__global__ void __launch_bounds__(256)
resamp_kernel(const float* __restrict__ x, const int* __restrict__ fl,
              float* __restrict__ out,
              float* __restrict__ mo_f32, unsigned char* __restrict__ mo_u8) {
    __shared__ BinParams p;
    int bt = blockIdx.x;                 // b*MAXT + t
    int b  = bt >> 11;                   // / MAXT
    int t  = bt & (MAXT - 1);
    if (threadIdx.x == 0) {
        make_params(t, g_L[b], fl[b], p);
        if (mo_f32) mo_f32[bt] = p.valid ? 0.0f : 1.0f;
        if (mo_u8)  mo_u8[bt]  = p.valid ? (unsigned char)0 : (unsigned char)1;
    }
    __syncthreads();

    int d = threadIdx.x;
    unsigned int idx = (unsigned int)bt * Dn + d;   // flat (b,t,d) index
    float eps = bits_to_normal(jax_random_bits_part(idx));

    const float* xcol = x + ((size_t)b * LIN) * Dn + d;
    out[idx] = bin_value(xcol, p, eps);
}

extern "C" void kernel_launch(void* const* d_in, const int* in_sizes, int n_in,
                              void* d_out, int out_size) {
    const float* x    = (const float*)d_in[0];
    const int*   fl   = (const int*)d_in[1];
    const void*  mask = (const void*)d_in[2];
    float* out = (float*)d_out;

    // Decide mask-tail layout from out_size.
    long long extra = (long long)out_size - (long long)OUT_ELEMS;
    float* mo_f32 = nullptr;
    unsigned char* mo_u8 = nullptr;
    if (extra >= (long long)(Bn * MAXT)) {
        mo_f32 = out + OUT_ELEMS;                       // mask as float32 elems
    } else if (extra == (long long)(Bn * MAXT) / 4) {
        mo_u8 = (unsigned char*)(out + OUT_ELEMS);      // mask as packed bytes
    }

    count_valid_kernel<<<Bn, 1024>>>(mask);
    resamp_kernel<<<Bn * MAXT, 256>>>(x, fl, out, mo_f32, mo_u8);
}

// round 16
// speedup vs baseline: 1.0452x; 1.0008x over previous
#include <cuda_runtime.h>
#include <stdint.h>
#include <math.h>

#define Bn    8
#define LIN   4096
#define Dn    256
#define MAXT  2048
#define OUT_ELEMS (Bn * MAXT * Dn)        // 4,194,304
#define NOISE_SCALE 0.1f
#define EPSV 1e-12f

__device__ int g_L[Bn];

// ---------------------------------------------------------------------------
// Count valid tokens per batch. Mask dtype sniffed at runtime:
//   int32  : words in {0,1}
//   float32: words contain 0x3F800000
//   uint8  : byte-packed 0/1 -> pad runs give 0x01010101 words
// 1024 threads/block: 8 sniff loads + 4 count loads per thread (high MLP,
// short dependent chains) instead of 32+16 with 256 threads.
// ---------------------------------------------------------------------------
__global__ void __launch_bounds__(1024)
count_valid_kernel(const void* __restrict__ maskv) {
    int b = blockIdx.x;
    const unsigned int* words = (const unsigned int*)maskv;
    int f32f = 0, u8f = 0;
    #pragma unroll
    for (int k = 0; k < 8; k++) {
        unsigned int w = words[k * 1024 + threadIdx.x];
        f32f |= (w == 0x3F800000u);
        u8f  |= (w == 0x01010101u);
    }
    int isf32 = __syncthreads_or(f32f);
    int isu8  = __syncthreads_or(u8f);

    int cnt = 0;
    if (isf32) {
        const float* m = (const float*)maskv + b * LIN;
        #pragma unroll
        for (int k = 0; k < 4; k++)
            cnt += (m[k * 1024 + threadIdx.x] == 0.0f) ? 1 : 0;
    } else if (isu8) {
        const unsigned char* m = (const unsigned char*)maskv + b * LIN;
        #pragma unroll
        for (int k = 0; k < 4; k++)
            cnt += (m[k * 1024 + threadIdx.x] == 0) ? 1 : 0;
    } else {
        const int* m = (const int*)maskv + b * LIN;
        #pragma unroll
        for (int k = 0; k < 4; k++)
            cnt += (m[k * 1024 + threadIdx.x] == 0) ? 1 : 0;
    }
    __shared__ int sh[32];
    for (int o = 16; o; o >>= 1) cnt += __shfl_down_sync(0xFFFFFFFFu, cnt, o);
    if ((threadIdx.x & 31) == 0) sh[threadIdx.x >> 5] = cnt;
    __syncthreads();
    if (threadIdx.x < 32) {
        int s = sh[threadIdx.x];
        for (int o = 16; o; o >>= 1) s += __shfl_down_sync(0xFFFFFFFFu, s, o);
        if (threadIdx.x == 0) g_L[b] = s;
    }
}

// ---------------------------------------------------------------------------
// Threefry-2x32, 20 rounds, key = (0, 42)  (jax.random.key(42))
// ---------------------------------------------------------------------------
__device__ __forceinline__ void threefry2x32(unsigned int& v0, unsigned int& v1) {
    const unsigned int ks0 = 0u;
    const unsigned int ks1 = 42u;
    const unsigned int ks2 = 0x1BD11BDAu ^ 42u;
    v0 += ks0; v1 += ks1;
#define TF_RND(r) { v0 += v1; v1 = __funnelshift_l(v1, v1, (r)); v1 ^= v0; }
    TF_RND(13) TF_RND(15) TF_RND(26) TF_RND(6)
    v0 += ks1; v1 += ks2 + 1u;
    TF_RND(17) TF_RND(29) TF_RND(16) TF_RND(24)
    v0 += ks2; v1 += ks0 + 2u;
    TF_RND(13) TF_RND(15) TF_RND(26) TF_RND(6)
    v0 += ks0; v1 += ks1 + 3u;
    TF_RND(17) TF_RND(29) TF_RND(16) TF_RND(24)
    v0 += ks1; v1 += ks2 + 4u;
    TF_RND(13) TF_RND(15) TF_RND(26) TF_RND(6)
    v0 += ks2; v1 += ks0 + 5u;
#undef TF_RND
}

// XLA/Giles single-precision erfinv (matches xla math.cc ErfInv 32-bit path)
__device__ __forceinline__ float erfinv_xla(float x) {
    float w = -log1pf(-x * x);
    float p;
    if (w < 5.0f) {
        w -= 2.5f;
        p =              2.81022636e-08f;
        p = fmaf(p, w,   3.43273939e-07f);
        p = fmaf(p, w,  -3.5233877e-06f);
        p = fmaf(p, w,  -4.39150654e-06f);
        p = fmaf(p, w,   0.00021858087f);
        p = fmaf(p, w,  -0.00125372503f);
        p = fmaf(p, w,  -0.00417768164f);
        p = fmaf(p, w,   0.246640727f);
        p = fmaf(p, w,   1.50140941f);
    } else {
        w = sqrtf(w) - 3.0f;
        p =             -0.000200214257f;
        p = fmaf(p, w,   0.000100950558f);
        p = fmaf(p, w,   0.00134934322f);
        p = fmaf(p, w,  -0.00367342844f);
        p = fmaf(p, w,   0.00573950773f);
        p = fmaf(p, w,  -0.0076224613f);
        p = fmaf(p, w,   0.00943887047f);
        p = fmaf(p, w,   1.00167406f);
        p = fmaf(p, w,   2.83297682f);
    }
    return p * x;
}

// bits -> jax.random.normal sample:
//   f = bitcast((bits>>9) | 0x3f800000) - 1      in [0,1)
//   u = max(lo, f*2.0f + lo), lo = nextafter(-1,0)
//   eps = sqrt(2) * erfinv(u)
__device__ __forceinline__ float bits_to_normal(unsigned int bits) {
    const float lo = -0.99999994f;
    float f = __uint_as_float((bits >> 9) | 0x3F800000u) - 1.0f;
    float u = fmaxf(lo, fmaf(f, 2.0f, lo));
    return 1.41421354f * erfinv_xla(u);
}

// Partitionable-threefry 32-bit random bits for flat index idx (< 2^32):
//   counter = (hi, lo) = (0, idx);  bits = v0_out ^ v1_out
__device__ __forceinline__ unsigned int jax_random_bits_part(unsigned int idx) {
    unsigned int v0 = 0u, v1 = idx;
    threefry2x32(v0, v1);
    return v0 ^ v1;
}

// ---------------------------------------------------------------------------
// Bin parameters (shared per block; all d lanes of a (b,t) share them)
// ---------------------------------------------------------------------------
struct BinParams {
    int   i0, i1, lo, hi, valid;
    float start, end, invcnt;
};

__device__ __forceinline__ void make_params(int t, int L, int T, BinParams& p) {
    p.valid = (t < T) && (L > 0);
    if (!p.valid) { p.i0 = p.i1 = p.lo = 0; p.hi = -1; p.start = p.end = 0.f; p.invcnt = 1.f; return; }
    int Tc = (T > 1) ? T : 1;
    int jL = t * L;
    p.i0 = jL / Tc;
    p.i1 = (jL + L + Tc - 1) / Tc;
    float step = (float)L / (float)Tc;
    p.start = (float)t * step;
    p.end   = p.start + step;
    int flo = (int)floorf(p.start); if (flo < 0) flo = 0;
    int fhi = (int)floorf(p.end);   if (fhi > L - 1) fhi = L - 1;
    p.lo = min(p.i0, flo);
    p.hi = max(p.i1 - 1, fhi);
    p.invcnt = 1.0f / (float)(p.i1 - p.i0);
}

__device__ __forceinline__ float bin_value(const float* __restrict__ xcol,
                                           const BinParams& p, float eps) {
    if (!p.valid) return 0.0f;
    float sInt = 0.f, sW = 0.f, sWS = 0.f, sWS2 = 0.f;
    #pragma unroll 4
    for (int i = p.lo; i <= p.hi; ++i) {
        float s = __ldg(xcol + (size_t)i * Dn);
        if (i >= p.i0 && i < p.i1) sInt += s;
        float fi = (float)i;
        float w = fmaxf(fminf(fi + 1.0f, p.end) - fmaxf(fi, p.start), 0.0f);
        sW  += w;
        sWS  = fmaf(w, s, sWS);
        sWS2 = fmaf(w * s, s, sWS2);
    }
    float Wsum = fmaxf(sW, EPSV);
    float mean = sWS  / Wsum;
    float msq  = sWS2 / Wsum;
    float var  = fmaxf(msq - mean * mean, EPSV);
    float std  = sqrtf(var);
    return fmaf(eps * std, NOISE_SCALE, sInt * p.invcnt);
}

// ---------------------------------------------------------------------------
// Main kernel: one block per (b, t) bin; thread = d lane.
// Thread 0 also writes the output mask element (if requested), removing the
// separate mask kernel launch.
// ---------------------------------------------------------------------------
__global__ void __launch_bounds__(256)
resamp_kernel(const float* __restrict__ x, const int* __restrict__ fl,
              float* __restrict__ out,
              float* __restrict__ mo_f32, unsigned char* __restrict__ mo_u8) {
    __shared__ BinParams p;
    int bt = blockIdx.x;                 // b*MAXT + t
    int b  = bt >> 11;                   // / MAXT
    int t  = bt & (MAXT - 1);
    if (threadIdx.x == 0) {
        make_params(t, g_L[b], fl[b], p);
        if (mo_f32) mo_f32[bt] = p.valid ? 0.0f : 1.0f;
        if (mo_u8)  mo_u8[bt]  = p.valid ? (unsigned char)0 : (unsigned char)1;
    }
    __syncthreads();

    int d = threadIdx.x;
    unsigned int idx = (unsigned int)bt * Dn + d;   // flat (b,t,d) index
    float eps = bits_to_normal(jax_random_bits_part(idx));

    const float* xcol = x + ((size_t)b * LIN) * Dn + d;
    out[idx] = bin_value(xcol, p, eps);
}

extern "C" void kernel_launch(void* const* d_in, const int* in_sizes, int n_in,
                              void* d_out, int out_size) {
    const float* x    = (const float*)d_in[0];
    const int*   fl   = (const int*)d_in[1];
    const void*  mask = (const void*)d_in[2];
    float* out = (float*)d_out;

    // Decide mask-tail layout from out_size.
    long long extra = (long long)out_size - (long long)OUT_ELEMS;
    float* mo_f32 = nullptr;
    unsigned char* mo_u8 = nullptr;
    if (extra >= (long long)(Bn * MAXT)) {
        mo_f32 = out + OUT_ELEMS;                       // mask as float32 elems
    } else if (extra == (long long)(Bn * MAXT) / 4) {
        mo_u8 = (unsigned char*)(out + OUT_ELEMS);      // mask as packed bytes
    }

    count_valid_kernel<<<Bn, 1024>>>(mask);
    resamp_kernel<<<Bn * MAXT, 256>>>(x, fl, out, mo_f32, mo_u8);
}